// round 12
// baseline (speedup 1.0000x reference)
#include <cuda_runtime.h>
#include <math.h>

#define BB 8
#define TT 50
#define SS 256
#define HH 512
#define NL 4
#define NVOC 50000
#define NVEXT 50256
#define ROWS (BB*TT)                 /* 400 */
#define OUT_ATT_OFF (ROWS*NVEXT)

// ---------------- device scratch (static: no allocation) ----------------
__device__ float    g_tar_emb[ROWS*HH];
__device__ float    g_x[NL*ROWS*HH];          // per-layer GRU outputs; layer 3 = masked dec_out
__device__ float    g_h2[2][NL*BB*HH];        // double-buffered hidden state
__device__ int      g_len[BB];
__device__ float    g_e1[BB*SS*HH];
__device__ float    g_e2[ROWS*HH];
__device__ float    g_allout[ROWS*2*HH];
__device__ float    g_mid[ROWS*HH];
__device__ float    g_logits[ROWS*NVEXT];
__device__ float    g_atten[ROWS*SS];
__device__ float    g_gate[ROWS];
__device__ float    g_rowmax[ROWS];
__device__ float    g_rowsum[ROWS];
__device__ unsigned g_bar;

// ---------------- setup ----------------
__global__ void setup_kernel(const int* __restrict__ tar, const float* __restrict__ hidden)
{
    int tid = threadIdx.x;
    if (tid == 0) g_bar = 0u;
    if (tid < BB) {
        int c = 0;
        for (int t = 0; t < TT; ++t) c += (tar[tid*TT + t] > 0) ? 1 : 0;
        g_len[tid] = (c < 1) ? 1 : c;
    }
    for (int i = tid; i < NL*BB*HH; i += blockDim.x)
        g_h2[0][i] = hidden[i];
}

// ---------------- embedding gather ----------
__global__ void embed_kernel(const int* __restrict__ tar, const float* __restrict__ emb)
{
    int row = blockIdx.x;
    int tid = threadIdx.x;
    int idx = tar[row];
    float4 v = make_float4(0.f, 0.f, 0.f, 0.f);
    if (idx != 0)
        v = ((const float4*)(emb + (size_t)idx * HH))[tid];
    ((float4*)(g_tar_emb + (size_t)row * HH))[tid] = v;
}

// ---------------- GRU v2: batch-shared weights, k-split warps ----------------
#define GRU_BLOCKS 128
// NOTE: macro params must NOT be named x/y/z/w — member tokens after '.' get substituted.
#define DOT4(acc, u_, v_) acc += (u_).x*(v_).x + (u_).y*(v_).y + (u_).z*(v_).z + (u_).w*(v_).w
#define PHYS(k4) ((k4) ^ (((k4) >> 4) & 7))   /* smem bank swizzle on float4 index */

__global__ void __launch_bounds__(128, 1)
gru_kernel(const float* __restrict__ wih, const float* __restrict__ whh,
           const float* __restrict__ bih, const float* __restrict__ bhh)
{
    const int bid  = blockIdx.x;
    const int l    = bid >> 5;            // 32 blocks per layer
    const int jblk = (bid & 31) << 4;     // 16-wide j slice
    const int tid  = threadIdx.x;
    const int jl   = tid >> 3;            // 0..15
    const int ks   = tid & 7;             // 0..7  (64-k slice)
    const int j    = jblk + jl;

    __shared__ float4 xs4[BB][HH/4];
    __shared__ float4 hs4[BB][HH/4];
    __shared__ int    lens[BB];

    if (tid < BB) lens[tid] = g_len[tid];

    const float4* wiR = (const float4*)(wih + ((size_t)l*3*HH + j) * HH);
    const float4* wiZ = wiR + (HH*HH/4);
    const float4* wiN = wiZ + (HH*HH/4);
    const float4* whR = (const float4*)(whh + ((size_t)l*3*HH + j) * HH);
    const float4* whZ = whR + (HH*HH/4);
    const float4* whN = whZ + (HH*HH/4);

    const float biR = bih[l*3*HH + j];
    const float biZ = bih[l*3*HH + HH + j];
    const float biN = bih[l*3*HH + 2*HH + j];
    const float bhR = bhh[l*3*HH + j];
    const float bhZ = bhh[l*3*HH + HH + j];
    const float bhN = bhh[l*3*HH + 2*HH + j];

    unsigned goal = 0u;
    for (int step = 0; step < TT + NL - 1; ++step) {
        const int t = step - l;
        const int p = step & 1;
        const bool active = (t >= 0) && (t < TT);

        if (active) {
#pragma unroll
            for (int q = 0; q < 8; ++q) {
                int idx = tid + q*128;
                int b  = idx >> 7;
                int k4 = idx & 127;
                const float4* xsrc = (l == 0)
                    ? (const float4*)(g_tar_emb + (size_t)(b*TT + t) * HH)
                    : (const float4*)(g_x + ((size_t)(l-1)*ROWS + b*TT + t) * HH);
                xs4[b][PHYS(k4)] = xsrc[k4];
                hs4[b][PHYS(k4)] = ((const float4*)(g_h2[p] + (size_t)(l*BB + b) * HH))[k4];
            }
            __syncthreads();

            float aR[BB], aZ[BB], aN[BB], cR[BB], cZ[BB], cN[BB];
#pragma unroll
            for (int b = 0; b < BB; ++b) { aR[b]=0.f; aZ[b]=0.f; aN[b]=0.f; cR[b]=0.f; cZ[b]=0.f; cN[b]=0.f; }

#pragma unroll 4
            for (int i = 0; i < 16; ++i) {
                const int k4 = ks*16 + i;
                const float4 wr = wiR[k4], wz = wiZ[k4], wn = wiN[k4];
                const float4 vr = whR[k4], vz = whZ[k4], vn = whN[k4];
                const int kk = PHYS(k4);
#pragma unroll
                for (int b = 0; b < BB; ++b) {
                    const float4 xv = xs4[b][kk];
                    const float4 hv = hs4[b][kk];
                    DOT4(aR[b], wr, xv); DOT4(aZ[b], wz, xv); DOT4(aN[b], wn, xv);
                    DOT4(cR[b], vr, hv); DOT4(cZ[b], vz, hv); DOT4(cN[b], vn, hv);
                }
            }

#pragma unroll
            for (int b = 0; b < BB; ++b) {
#pragma unroll
                for (int o = 1; o < 8; o <<= 1) {
                    aR[b] += __shfl_xor_sync(0xffffffffu, aR[b], o);
                    aZ[b] += __shfl_xor_sync(0xffffffffu, aZ[b], o);
                    aN[b] += __shfl_xor_sync(0xffffffffu, aN[b], o);
                    cR[b] += __shfl_xor_sync(0xffffffffu, cR[b], o);
                    cZ[b] += __shfl_xor_sync(0xffffffffu, cZ[b], o);
                    cN[b] += __shfl_xor_sync(0xffffffffu, cN[b], o);
                }
            }

            if (ks == 0) {
#pragma unroll
                for (int b = 0; b < BB; ++b) {
                    float r = 1.f / (1.f + expf(-(aR[b] + biR + cR[b] + bhR)));
                    float z = 1.f / (1.f + expf(-(aZ[b] + biZ + cZ[b] + bhZ)));
                    float n = tanhf(aN[b] + biN + r * (cN[b] + bhN));
                    float hold = ((const float*)&hs4[b][PHYS(j >> 2)])[j & 3];
                    float hnew = (1.f - z) * n + z * hold;
                    g_h2[p ^ 1][(size_t)(l*BB + b) * HH + j] = hnew;
                    float ov = hnew;
                    if (l == NL-1 && t >= lens[b]) ov = 0.f;
                    g_x[((size_t)l*ROWS + b*TT + t) * HH + j] = ov;
                }
            }
        } else {
            int b  = tid >> 4;
            int j2 = jblk + (tid & 15);
            g_h2[p ^ 1][(size_t)(l*BB + b) * HH + j2] =
                g_h2[p][(size_t)(l*BB + b) * HH + j2];
        }

        __syncthreads();
        if (tid == 0) {
            __threadfence();
            atomicAdd(&g_bar, 1u);
            goal += GRU_BLOCKS;
            while (*(volatile unsigned*)&g_bar < goal) __nanosleep(64);
            __threadfence();
        }
        __syncthreads();
    }
}

// ---------------- SGEMM (fp32) — kept for e2 only ----
#define BM 64
#define BN 128
#define BKK 16
__global__ void __launch_bounds__(128, 3)
sgemm_tn(const float* __restrict__ A, const float* __restrict__ W,
         const float* __restrict__ bias, float* __restrict__ C,
         int M, int N, int K)
{
    __shared__ float As[2][BKK][BM + 4];
    __shared__ float Bs[2][BKK][BN + 4];

    const int tid = threadIdx.x;
    const int m0 = blockIdx.y * BM;
    const int n0 = blockIdx.x * BN;
    const int tx = tid & 15;
    const int ty = tid >> 4;

    float acc[8][8];
#pragma unroll
    for (int i = 0; i < 8; ++i)
#pragma unroll
        for (int jj = 0; jj < 8; ++jj) acc[i][jj] = 0.f;

    float4 pa[2], pb[4];

#pragma unroll
    for (int q = 0; q < 2; ++q) {
        int idx = tid + q*128; int row = idx >> 2, kq = idx & 3; int m = m0 + row;
        pa[q] = make_float4(0.f,0.f,0.f,0.f);
        if (m < M) pa[q] = *(const float4*)(A + (size_t)m*K + kq*4);
    }
#pragma unroll
    for (int q = 0; q < 4; ++q) {
        int idx = tid + q*128; int row = idx >> 2, kq = idx & 3; int n = n0 + row;
        pb[q] = make_float4(0.f,0.f,0.f,0.f);
        if (n < N) pb[q] = *(const float4*)(W + (size_t)n*K + kq*4);
    }
#pragma unroll
    for (int q = 0; q < 2; ++q) {
        int idx = tid + q*128; int row = idx >> 2, kq = idx & 3;
        As[0][kq*4+0][row] = pa[q].x; As[0][kq*4+1][row] = pa[q].y;
        As[0][kq*4+2][row] = pa[q].z; As[0][kq*4+3][row] = pa[q].w;
    }
#pragma unroll
    for (int q = 0; q < 4; ++q) {
        int idx = tid + q*128; int row = idx >> 2, kq = idx & 3;
        Bs[0][kq*4+0][row] = pb[q].x; Bs[0][kq*4+1][row] = pb[q].y;
        Bs[0][kq*4+2][row] = pb[q].z; Bs[0][kq*4+3][row] = pb[q].w;
    }
    __syncthreads();

    const int nk = K / BKK;
    for (int kb = 0; kb < nk; ++kb) {
        const int cur = kb & 1, nxt = cur ^ 1;
        const bool more = (kb + 1 < nk);
        if (more) {
            const int k0 = (kb + 1) * BKK;
#pragma unroll
            for (int q = 0; q < 2; ++q) {
                int idx = tid + q*128; int row = idx >> 2, kq = idx & 3; int m = m0 + row;
                pa[q] = make_float4(0.f,0.f,0.f,0.f);
                if (m < M) pa[q] = *(const float4*)(A + (size_t)m*K + k0 + kq*4);
            }
#pragma unroll
            for (int q = 0; q < 4; ++q) {
                int idx = tid + q*128; int row = idx >> 2, kq = idx & 3; int n = n0 + row;
                pb[q] = make_float4(0.f,0.f,0.f,0.f);
                if (n < N) pb[q] = *(const float4*)(W + (size_t)n*K + k0 + kq*4);
            }
        }
#pragma unroll
        for (int k = 0; k < BKK; ++k) {
            float4 a0 = *(const float4*)&As[cur][k][ty*8];
            float4 a1 = *(const float4*)&As[cur][k][ty*8 + 4];
            float4 b0 = *(const float4*)&Bs[cur][k][tx*8];
            float4 b1 = *(const float4*)&Bs[cur][k][tx*8 + 4];
            float av[8] = {a0.x,a0.y,a0.z,a0.w,a1.x,a1.y,a1.z,a1.w};
            float bv[8] = {b0.x,b0.y,b0.z,b0.w,b1.x,b1.y,b1.z,b1.w};
#pragma unroll
            for (int i = 0; i < 8; ++i)
#pragma unroll
                for (int jj = 0; jj < 8; ++jj)
                    acc[i][jj] += av[i] * bv[jj];
        }
        if (more) {
#pragma unroll
            for (int q = 0; q < 2; ++q) {
                int idx = tid + q*128; int row = idx >> 2, kq = idx & 3;
                As[nxt][kq*4+0][row] = pa[q].x; As[nxt][kq*4+1][row] = pa[q].y;
                As[nxt][kq*4+2][row] = pa[q].z; As[nxt][kq*4+3][row] = pa[q].w;
            }
#pragma unroll
            for (int q = 0; q < 4; ++q) {
                int idx = tid + q*128; int row = idx >> 2, kq = idx & 3;
                Bs[nxt][kq*4+0][row] = pb[q].x; Bs[nxt][kq*4+1][row] = pb[q].y;
                Bs[nxt][kq*4+2][row] = pb[q].z; Bs[nxt][kq*4+3][row] = pb[q].w;
            }
        }
        __syncthreads();
    }

#pragma unroll
    for (int i = 0; i < 8; ++i) {
        int m = m0 + ty*8 + i;
        if (m >= M) continue;
#pragma unroll
        for (int jj = 0; jj < 8; ++jj) {
            int n = n0 + tx*8 + jj;
            if (n < N) C[(size_t)m*N + n] = acc[i][jj] + bias[n];
        }
    }
}

// ---------------- tf32 tensor-core GEMM v2 --------------------
// C[m,n] = bias[n] + sum_k A[m,k]*W[n,k].
// 128 threads = 4 warps: 2(M) x 2(N); warp tile 32x64 (2 m16-tiles share
// each B fragment -> 1.5 LDS per MMA vs 2.5 in v1). BM=64 BN=128 BK=16,
// double-buffered; stride 20 floats -> frag pattern (g*20+tig) bank-free.
#define TM 64
#define TN 128
#define TK 16
#define TSTR 20

__device__ __forceinline__ float f2tf32(float f) {
    unsigned r;
    asm("cvt.rna.tf32.f32 %0, %1;" : "=r"(r) : "f"(f));
    return __uint_as_float(r);
}

__global__ void __launch_bounds__(128, 3)
mma_tf32_tn(const float* __restrict__ A, const float* __restrict__ W,
            const float* __restrict__ bias, float* __restrict__ C,
            int M, int N, int K)
{
    __shared__ float As[2][TM][TSTR];
    __shared__ float Bs[2][TN][TSTR];

    const int tid  = threadIdx.x;
    const int lane = tid & 31;
    const int g    = lane >> 2;      // 0..7
    const int tig  = lane & 3;       // 0..3
    const int warp = tid >> 5;       // 0..3
    const int wM   = warp >> 1;      // 0..1
    const int wN   = warp & 1;       // 0..1

    const int m0 = blockIdx.y * TM;
    const int n0 = blockIdx.x * TN;

    // staging coords: A row = tid>>1 (0..63), k-half = (tid&1)*8
    const int arow = tid >> 1;
    const int akq  = (tid & 1) * 8;
    const bool aok = (m0 + arow) < M;
    // B row = tid (0..127), all 16 k
    const bool bok = (n0 + tid) < N;

    float c[2][8][4];
#pragma unroll
    for (int mt = 0; mt < 2; ++mt)
#pragma unroll
        for (int j = 0; j < 8; ++j)
#pragma unroll
            for (int i = 0; i < 4; ++i) c[mt][j][i] = 0.f;

    float4 pa0, pa1, pb[4];

    // prefetch k-block 0
    pa0 = make_float4(0.f,0.f,0.f,0.f);
    pa1 = make_float4(0.f,0.f,0.f,0.f);
    if (aok) {
        pa0 = *(const float4*)(A + (size_t)(m0 + arow)*K + akq);
        pa1 = *(const float4*)(A + (size_t)(m0 + arow)*K + akq + 4);
    }
#pragma unroll
    for (int q = 0; q < 4; ++q) {
        pb[q] = make_float4(0.f,0.f,0.f,0.f);
        if (bok) pb[q] = *(const float4*)(W + (size_t)(n0 + tid)*K + q*4);
    }
    {
        float* ad = &As[0][arow][akq];
        ad[0]=f2tf32(pa0.x); ad[1]=f2tf32(pa0.y); ad[2]=f2tf32(pa0.z); ad[3]=f2tf32(pa0.w);
        ad[4]=f2tf32(pa1.x); ad[5]=f2tf32(pa1.y); ad[6]=f2tf32(pa1.z); ad[7]=f2tf32(pa1.w);
        float* bd = &Bs[0][tid][0];
#pragma unroll
        for (int q = 0; q < 4; ++q) {
            bd[q*4+0]=f2tf32(pb[q].x); bd[q*4+1]=f2tf32(pb[q].y);
            bd[q*4+2]=f2tf32(pb[q].z); bd[q*4+3]=f2tf32(pb[q].w);
        }
    }
    __syncthreads();

    const int nk = K / TK;
    for (int kb = 0; kb < nk; ++kb) {
        const int cur = kb & 1, nxt = cur ^ 1;
        const bool more = (kb + 1 < nk);
        if (more) {
            const int k0 = (kb + 1) * TK;
            pa0 = make_float4(0.f,0.f,0.f,0.f);
            pa1 = make_float4(0.f,0.f,0.f,0.f);
            if (aok) {
                pa0 = *(const float4*)(A + (size_t)(m0 + arow)*K + k0 + akq);
                pa1 = *(const float4*)(A + (size_t)(m0 + arow)*K + k0 + akq + 4);
            }
#pragma unroll
            for (int q = 0; q < 4; ++q) {
                pb[q] = make_float4(0.f,0.f,0.f,0.f);
                if (bok) pb[q] = *(const float4*)(W + (size_t)(n0 + tid)*K + k0 + q*4);
            }
        }

#pragma unroll
        for (int ksub = 0; ksub < 2; ++ksub) {
            const int k8 = ksub * 8;
            unsigned a[2][4];
#pragma unroll
            for (int mt = 0; mt < 2; ++mt) {
                const float* ar = &As[cur][wM*32 + mt*16 + g][k8 + tig];
                a[mt][0] = __float_as_uint(ar[0]);
                a[mt][1] = __float_as_uint(ar[8*TSTR]);
                a[mt][2] = __float_as_uint(ar[4]);
                a[mt][3] = __float_as_uint(ar[8*TSTR + 4]);
            }
#pragma unroll
            for (int j = 0; j < 8; ++j) {
                const float* br = &Bs[cur][wN*64 + j*8 + g][k8 + tig];
                unsigned b0 = __float_as_uint(br[0]);
                unsigned b1 = __float_as_uint(br[4]);
#pragma unroll
                for (int mt = 0; mt < 2; ++mt) {
                    asm volatile(
                        "mma.sync.aligned.m16n8k8.row.col.f32.tf32.tf32.f32 "
                        "{%0,%1,%2,%3}, {%4,%5,%6,%7}, {%8,%9}, {%0,%1,%2,%3};\n"
                        : "+f"(c[mt][j][0]), "+f"(c[mt][j][1]),
                          "+f"(c[mt][j][2]), "+f"(c[mt][j][3])
                        : "r"(a[mt][0]), "r"(a[mt][1]), "r"(a[mt][2]), "r"(a[mt][3]),
                          "r"(b0), "r"(b1));
                }
            }
        }

        if (more) {
            float* ad = &As[nxt][arow][akq];
            ad[0]=f2tf32(pa0.x); ad[1]=f2tf32(pa0.y); ad[2]=f2tf32(pa0.z); ad[3]=f2tf32(pa0.w);
            ad[4]=f2tf32(pa1.x); ad[5]=f2tf32(pa1.y); ad[6]=f2tf32(pa1.z); ad[7]=f2tf32(pa1.w);
            float* bd = &Bs[nxt][tid][0];
#pragma unroll
            for (int q = 0; q < 4; ++q) {
                bd[q*4+0]=f2tf32(pb[q].x); bd[q*4+1]=f2tf32(pb[q].y);
                bd[q*4+2]=f2tf32(pb[q].z); bd[q*4+3]=f2tf32(pb[q].w);
            }
        }
        __syncthreads();
    }

    // epilogue: c0,c1 -> row g cols 2*tig..+1; c2,c3 -> row g+8
#pragma unroll
    for (int mt = 0; mt < 2; ++mt) {
        const int row0 = m0 + wM*32 + mt*16 + g;
        const int row1 = row0 + 8;
#pragma unroll
        for (int j = 0; j < 8; ++j) {
            int n = n0 + wN*64 + j*8 + tig*2;
            if (n < N) {
                float bv = bias[n];
                if (row0 < M) C[(size_t)row0*N + n] = c[mt][j][0] + bv;
                if (row1 < M) C[(size_t)row1*N + n] = c[mt][j][2] + bv;
            }
            if (n + 1 < N) {
                float bv = bias[n+1];
                if (row0 < M) C[(size_t)row0*N + n+1] = c[mt][j][1] + bv;
                if (row1 < M) C[(size_t)row1*N + n+1] = c[mt][j][3] + bv;
            }
        }
    }
}

// ---------------- attention scores + softmax -> atten ----------------
__global__ void __launch_bounds__(256)
attn_kernel(const int* __restrict__ sou, const float* __restrict__ v_w,
            float* __restrict__ out)
{
    const int row = blockIdx.x;
    const int b = row / TT;
    const int tid = threadIdx.x;
    const int warp = tid >> 5, lane = tid & 31;
    const float NEG_INF = __int_as_float(0xff800000);

    __shared__ float e2s[HH];
    __shared__ float vs[HH];
    __shared__ float sc[SS];
    __shared__ float red[8];

    e2s[tid]       = g_e2[(size_t)row*HH + tid];
    e2s[tid + 256] = g_e2[(size_t)row*HH + tid + 256];
    vs[tid]        = v_w[tid];
    vs[tid + 256]  = v_w[tid + 256];
    __syncthreads();

    for (int s = warp; s < SS; s += 8) {
        const float* e1r = g_e1 + ((size_t)(b*SS + s)) * HH;
        float acc = 0.f;
#pragma unroll
        for (int k = 0; k < HH/32; ++k) {
            int h = lane + k*32;
            acc += tanhf(e1r[h] + e2s[h]) * vs[h];
        }
#pragma unroll
        for (int o = 16; o; o >>= 1) acc += __shfl_xor_sync(0xffffffffu, acc, o);
        if (lane == 0)
            sc[s] = (sou[b*SS + s] == 0) ? NEG_INF : acc;
    }
    __syncthreads();

    float v0 = sc[tid];
    float m = v0;
#pragma unroll
    for (int o = 16; o; o >>= 1) m = fmaxf(m, __shfl_xor_sync(0xffffffffu, m, o));
    if (lane == 0) red[warp] = m;
    __syncthreads();
    float M = red[0];
#pragma unroll
    for (int w = 1; w < 8; ++w) M = fmaxf(M, red[w]);
    __syncthreads();
    float e = __expf(v0 - M);
    float ssum = e;
#pragma unroll
    for (int o = 16; o; o >>= 1) ssum += __shfl_xor_sync(0xffffffffu, ssum, o);
    if (lane == 0) red[warp] = ssum;
    __syncthreads();
    float Ssum = 0.f;
#pragma unroll
    for (int w = 0; w < 8; ++w) Ssum += red[w];

    float p = e / Ssum;
    g_atten[(size_t)row*SS + tid] = p;
    out[OUT_ATT_OFF + (size_t)row*SS + tid] = p;
}

// ---------------- weighted = atten @ enc ; build all_out --------------
__global__ void __launch_bounds__(128)
weighted_kernel(const float* __restrict__ enc)
{
    const int row = blockIdx.x;
    const int b = row / TT;
    const int tid = threadIdx.x;

    __shared__ float att[SS];
    att[tid]       = g_atten[(size_t)row*SS + tid];
    att[tid + 128] = g_atten[(size_t)row*SS + tid + 128];
    __syncthreads();

    const float4* encb = (const float4*)enc;
    float4 acc = make_float4(0.f,0.f,0.f,0.f);
#pragma unroll 4
    for (int s = 0; s < SS; ++s) {
        float a = att[s];
        float4 ev = encb[((size_t)(b*SS + s)) * (HH/4) + tid];
        acc.x += a*ev.x; acc.y += a*ev.y; acc.z += a*ev.z; acc.w += a*ev.w;
    }
    float4* ao = (float4*)(g_allout + (size_t)row * 2*HH);
    ao[tid] = acc;
    float4 dv = ((const float4*)(g_x + ((size_t)3*ROWS + row)*HH))[tid];
    ao[HH/4 + tid] = dv;
}

// ---------------- copy gate --------------------------------------------
__global__ void __launch_bounds__(128)
gate_kernel(const float* __restrict__ g1w, const float* __restrict__ g1b,
            const float* __restrict__ g2w, const float* __restrict__ g2b,
            const float* __restrict__ g3w, const float* __restrict__ g3b)
{
    const int row = blockIdx.x;
    const int tid = threadIdx.x;
    const int lane = tid & 31, warp = tid >> 5;
    __shared__ float red[4];

    const float* ao = g_allout + (size_t)row * 2*HH;
    const float* te = g_tar_emb + (size_t)row * HH;
    float part = 0.f;
    for (int i = tid; i < HH; i += 128)
        part += ao[i]*g1w[i] + ao[HH + i]*g2w[i] + te[i]*g3w[i];
#pragma unroll
    for (int o = 16; o; o >>= 1) part += __shfl_xor_sync(0xffffffffu, part, o);
    if (lane == 0) red[warp] = part;
    __syncthreads();
    if (tid == 0) {
        float s = red[0] + red[1] + red[2] + red[3] + g1b[0] + g2b[0] + g3b[0];
        g_gate[row] = 1.f / (1.f + expf(-s));
    }
}

// ---------------- logits row softmax stats ------------------------------
__global__ void __launch_bounds__(256)
stats_kernel(const int* __restrict__ ext_len)
{
    const int row = blockIdx.x;
    const int b = row / TT;
    const int tid = threadIdx.x;
    const int lane = tid & 31, warp = tid >> 5;
    const int limit = NVOC + ext_len[b];
    const float* lr = g_logits + (size_t)row * NVEXT;
    const float NEG_INF = __int_as_float(0xff800000);
    __shared__ float red[8];

    float m = NEG_INF;
    for (int c = tid; c < limit; c += 256) m = fmaxf(m, lr[c]);
#pragma unroll
    for (int o = 16; o; o >>= 1) m = fmaxf(m, __shfl_xor_sync(0xffffffffu, m, o));
    if (lane == 0) red[warp] = m;
    __syncthreads();
    float M = red[0];
#pragma unroll
    for (int w = 1; w < 8; ++w) M = fmaxf(M, red[w]);
    __syncthreads();

    float s = 0.f;
    for (int c = tid; c < limit; c += 256) s += __expf(lr[c] - M);
#pragma unroll
    for (int o = 16; o; o >>= 1) s += __shfl_xor_sync(0xffffffffu, s, o);
    if (lane == 0) red[warp] = s;
    __syncthreads();
    if (tid == 0) {
        float S = 0.f;
#pragma unroll
        for (int w = 0; w < 8; ++w) S += red[w];
        g_rowmax[row] = M;
        g_rowsum[row] = S;
    }
}

// ---------------- (1-gate)*softmax(logits) -> out -----------------------
__global__ void __launch_bounds__(256)
gen_kernel(const int* __restrict__ ext_len, float* __restrict__ out)
{
    const int row = blockIdx.y;
    const int c = blockIdx.x * 256 + threadIdx.x;
    if (c >= NVEXT) return;
    const int b = row / TT;
    const int limit = NVOC + ext_len[b];
    const float gate = g_gate[row];
    float val = 0.f;
    if (c < limit)
        val = __expf(g_logits[(size_t)row*NVEXT + c] - g_rowmax[row]) / g_rowsum[row];
    out[(size_t)row*NVEXT + c] = (1.f - gate) * val;
}

// ---------------- copy mechanism: scatter-add gate*atten ---------------
__global__ void __launch_bounds__(256)
scatter_kernel(const int* __restrict__ sou, float* __restrict__ out)
{
    const int row = blockIdx.x;
    const int b = row / TT;
    const int s = threadIdx.x;
    const float add = g_gate[row] * g_atten[(size_t)row*SS + s];
    atomicAdd(&out[(size_t)row*NVEXT + sou[b*SS + s]], add);
}

// ---------------- launcher ---------------------------------------------
extern "C" void kernel_launch(void* const* d_in, const int* in_sizes, int n_in,
                              void* d_out, int out_size)
{
    const int*   sou      = (const int*)  d_in[0];
    const int*   tar      = (const int*)  d_in[1];
    const float* hidden   = (const float*)d_in[2];
    const float* enc      = (const float*)d_in[3];
    const int*   ext_len  = (const int*)  d_in[4];
    const float* emb      = (const float*)d_in[5];
    const float* gru_wih  = (const float*)d_in[6];
    const float* gru_whh  = (const float*)d_in[7];
    const float* gru_bih  = (const float*)d_in[8];
    const float* gru_bhh  = (const float*)d_in[9];
    const float* fc_enc_w = (const float*)d_in[10];
    const float* fc_enc_b = (const float*)d_in[11];
    const float* fc_dec_w = (const float*)d_in[12];
    const float* fc_dec_b = (const float*)d_in[13];
    const float* v_w      = (const float*)d_in[14];
    const float* fc_out1_w= (const float*)d_in[15];
    const float* fc_out1_b= (const float*)d_in[16];
    const float* fc_out2_w= (const float*)d_in[17];
    const float* fc_out2_b= (const float*)d_in[18];
    const float* g1w      = (const float*)d_in[19];
    const float* g1b      = (const float*)d_in[20];
    const float* g2w      = (const float*)d_in[21];
    const float* g2b      = (const float*)d_in[22];
    const float* g3w      = (const float*)d_in[23];
    const float* g3b      = (const float*)d_in[24];
    float* out = (float*)d_out;

    float *p_e1, *p_e2, *p_x, *p_allout, *p_mid, *p_logits;
    cudaGetSymbolAddress((void**)&p_e1,     g_e1);
    cudaGetSymbolAddress((void**)&p_e2,     g_e2);
    cudaGetSymbolAddress((void**)&p_x,      g_x);
    cudaGetSymbolAddress((void**)&p_allout, g_allout);
    cudaGetSymbolAddress((void**)&p_mid,    g_mid);
    cudaGetSymbolAddress((void**)&p_logits, g_logits);
    const float* p_dec = p_x + (size_t)3*ROWS*HH;

    setup_kernel<<<1, 256>>>(tar, hidden);
    embed_kernel<<<ROWS, 128>>>(tar, emb);
    gru_kernel<<<GRU_BLOCKS, 128>>>(gru_wih, gru_whh, gru_bih, gru_bhh);

    // e1 = enc @ fc_enc_w^T + b   [2048, 512]  (tf32)
    mma_tf32_tn<<<dim3((HH+TN-1)/TN, (BB*SS+TM-1)/TM), 128>>>(enc, fc_enc_w, fc_enc_b, p_e1, BB*SS, HH, HH);
    // e2 = dec_out @ fc_dec_w^T + b  [400, 512]  (fp32 hedge)
    sgemm_tn<<<dim3((HH+BN-1)/BN, (ROWS+BM-1)/BM), 128>>>(p_dec, fc_dec_w, fc_dec_b, p_e2, ROWS, HH, HH);

    attn_kernel<<<ROWS, 256>>>(sou, v_w, out);
    weighted_kernel<<<ROWS, 128>>>(enc);
    gate_kernel<<<ROWS, 128>>>(g1w, g1b, g2w, g2b, g3w, g3b);

    // mid = all_out @ fc_out2_w^T + b  [400, 512], K=1024  (tf32)
    mma_tf32_tn<<<dim3((HH+TN-1)/TN, (ROWS+TM-1)/TM), 128>>>(p_allout, fc_out2_w, fc_out2_b, p_mid, ROWS, HH, 2*HH);
    // logits = mid @ fc_out1_w^T + b  [400, 50256]  (tf32 v2)
    mma_tf32_tn<<<dim3((NVEXT+TN-1)/TN, (ROWS+TM-1)/TM), 128>>>(p_mid, fc_out1_w, fc_out1_b, p_logits, ROWS, NVEXT, HH);

    stats_kernel<<<ROWS, 256>>>(ext_len);
    gen_kernel<<<dim3((NVEXT+255)/256, ROWS), 256>>>(ext_len, out);
    scatter_kernel<<<ROWS, 256>>>(sou, out);
}

// round 17
// speedup vs baseline: 1.0575x; 1.0575x over previous
#include <cuda_runtime.h>
#include <cuda_fp16.h>
#include <stdint.h>
#include <math.h>

#define BB 8
#define TT 50
#define SS 256
#define HH 512
#define NL 4
#define NVOC 50000
#define NVEXT 50256
#define ROWS (BB*TT)                 /* 400 */
#define OUT_ATT_OFF (ROWS*NVEXT)

// ---------------- device scratch (static: no allocation) ----------------
__device__ float    g_tar_emb[ROWS*HH];
__device__ float    g_x[NL*ROWS*HH];
__device__ float    g_h2[2][NL*BB*HH];
__device__ int      g_len[BB];
__device__ float    g_e1[BB*SS*HH];
__device__ float    g_e2[ROWS*HH];
__device__ float    g_allout[ROWS*2*HH];
__device__ float    g_mid[ROWS*HH];
__device__ float    g_logits[ROWS*NVEXT];
__device__ float    g_atten[ROWS*SS];
__device__ float    g_gate[ROWS];
__device__ float    g_rowmax[ROWS];
__device__ float    g_rowsum[ROWS];
__device__ unsigned g_bar;

// ---------------- setup ----------------
__global__ void setup_kernel(const int* __restrict__ tar, const float* __restrict__ hidden)
{
    int tid = threadIdx.x;
    if (tid == 0) g_bar = 0u;
    if (tid < BB) {
        int c = 0;
        for (int t = 0; t < TT; ++t) c += (tar[tid*TT + t] > 0) ? 1 : 0;
        g_len[tid] = (c < 1) ? 1 : c;
    }
    for (int i = tid; i < NL*BB*HH; i += blockDim.x)
        g_h2[0][i] = hidden[i];
}

// ---------------- embedding gather ----------
__global__ void embed_kernel(const int* __restrict__ tar, const float* __restrict__ emb)
{
    int row = blockIdx.x;
    int tid = threadIdx.x;
    int idx = tar[row];
    float4 v = make_float4(0.f, 0.f, 0.f, 0.f);
    if (idx != 0)
        v = ((const float4*)(emb + (size_t)idx * HH))[tid];
    ((float4*)(g_tar_emb + (size_t)row * HH))[tid] = v;
}

// ---------------- GRU v2 ----------------
#define GRU_BLOCKS 128
// NOTE: macro params must NOT be named x/y/z/w — member tokens after '.' get substituted.
#define DOT4(acc, u_, v_) acc += (u_).x*(v_).x + (u_).y*(v_).y + (u_).z*(v_).z + (u_).w*(v_).w
#define PHYS(k4) ((k4) ^ (((k4) >> 4) & 7))

__global__ void __launch_bounds__(128, 1)
gru_kernel(const float* __restrict__ wih, const float* __restrict__ whh,
           const float* __restrict__ bih, const float* __restrict__ bhh)
{
    const int bid  = blockIdx.x;
    const int l    = bid >> 5;
    const int jblk = (bid & 31) << 4;
    const int tid  = threadIdx.x;
    const int jl   = tid >> 3;
    const int ks   = tid & 7;
    const int j    = jblk + jl;

    __shared__ float4 xs4[BB][HH/4];
    __shared__ float4 hs4[BB][HH/4];
    __shared__ int    lens[BB];

    if (tid < BB) lens[tid] = g_len[tid];

    const float4* wiR = (const float4*)(wih + ((size_t)l*3*HH + j) * HH);
    const float4* wiZ = wiR + (HH*HH/4);
    const float4* wiN = wiZ + (HH*HH/4);
    const float4* whR = (const float4*)(whh + ((size_t)l*3*HH + j) * HH);
    const float4* whZ = whR + (HH*HH/4);
    const float4* whN = whZ + (HH*HH/4);

    const float biR = bih[l*3*HH + j];
    const float biZ = bih[l*3*HH + HH + j];
    const float biN = bih[l*3*HH + 2*HH + j];
    const float bhR = bhh[l*3*HH + j];
    const float bhZ = bhh[l*3*HH + HH + j];
    const float bhN = bhh[l*3*HH + 2*HH + j];

    unsigned goal = 0u;
    for (int step = 0; step < TT + NL - 1; ++step) {
        const int t = step - l;
        const int p = step & 1;
        const bool active = (t >= 0) && (t < TT);

        if (active) {
#pragma unroll
            for (int q = 0; q < 8; ++q) {
                int idx = tid + q*128;
                int b  = idx >> 7;
                int k4 = idx & 127;
                const float4* xsrc = (l == 0)
                    ? (const float4*)(g_tar_emb + (size_t)(b*TT + t) * HH)
                    : (const float4*)(g_x + ((size_t)(l-1)*ROWS + b*TT + t) * HH);
                xs4[b][PHYS(k4)] = xsrc[k4];
                hs4[b][PHYS(k4)] = ((const float4*)(g_h2[p] + (size_t)(l*BB + b) * HH))[k4];
            }
            __syncthreads();

            float aR[BB], aZ[BB], aN[BB], cR[BB], cZ[BB], cN[BB];
#pragma unroll
            for (int b = 0; b < BB; ++b) { aR[b]=0.f; aZ[b]=0.f; aN[b]=0.f; cR[b]=0.f; cZ[b]=0.f; cN[b]=0.f; }

#pragma unroll 4
            for (int i = 0; i < 16; ++i) {
                const int k4 = ks*16 + i;
                const float4 wr = wiR[k4], wz = wiZ[k4], wn = wiN[k4];
                const float4 vr = whR[k4], vz = whZ[k4], vn = whN[k4];
                const int kk = PHYS(k4);
#pragma unroll
                for (int b = 0; b < BB; ++b) {
                    const float4 xv = xs4[b][kk];
                    const float4 hv = hs4[b][kk];
                    DOT4(aR[b], wr, xv); DOT4(aZ[b], wz, xv); DOT4(aN[b], wn, xv);
                    DOT4(cR[b], vr, hv); DOT4(cZ[b], vz, hv); DOT4(cN[b], vn, hv);
                }
            }

#pragma unroll
            for (int b = 0; b < BB; ++b) {
#pragma unroll
                for (int o = 1; o < 8; o <<= 1) {
                    aR[b] += __shfl_xor_sync(0xffffffffu, aR[b], o);
                    aZ[b] += __shfl_xor_sync(0xffffffffu, aZ[b], o);
                    aN[b] += __shfl_xor_sync(0xffffffffu, aN[b], o);
                    cR[b] += __shfl_xor_sync(0xffffffffu, cR[b], o);
                    cZ[b] += __shfl_xor_sync(0xffffffffu, cZ[b], o);
                    cN[b] += __shfl_xor_sync(0xffffffffu, cN[b], o);
                }
            }

            if (ks == 0) {
#pragma unroll
                for (int b = 0; b < BB; ++b) {
                    float r = 1.f / (1.f + expf(-(aR[b] + biR + cR[b] + bhR)));
                    float z = 1.f / (1.f + expf(-(aZ[b] + biZ + cZ[b] + bhZ)));
                    float n = tanhf(aN[b] + biN + r * (cN[b] + bhN));
                    float hold = ((const float*)&hs4[b][PHYS(j >> 2)])[j & 3];
                    float hnew = (1.f - z) * n + z * hold;
                    g_h2[p ^ 1][(size_t)(l*BB + b) * HH + j] = hnew;
                    float ov = hnew;
                    if (l == NL-1 && t >= lens[b]) ov = 0.f;
                    g_x[((size_t)l*ROWS + b*TT + t) * HH + j] = ov;
                }
            }
        } else {
            int b  = tid >> 4;
            int j2 = jblk + (tid & 15);
            g_h2[p ^ 1][(size_t)(l*BB + b) * HH + j2] =
                g_h2[p][(size_t)(l*BB + b) * HH + j2];
        }

        __syncthreads();
        if (tid == 0) {
            __threadfence();
            atomicAdd(&g_bar, 1u);
            goal += GRU_BLOCKS;
            while (*(volatile unsigned*)&g_bar < goal) __nanosleep(64);
            __threadfence();
        }
        __syncthreads();
    }
}

// ---------------- SGEMM (fp32) — e2 only ----
#define BM 64
#define BN 128
#define BKK 16
__global__ void __launch_bounds__(128, 3)
sgemm_tn(const float* __restrict__ A, const float* __restrict__ W,
         const float* __restrict__ bias, float* __restrict__ C,
         int M, int N, int K)
{
    __shared__ float As[2][BKK][BM + 4];
    __shared__ float Bs[2][BKK][BN + 4];

    const int tid = threadIdx.x;
    const int m0 = blockIdx.y * BM;
    const int n0 = blockIdx.x * BN;
    const int tx = tid & 15;
    const int ty = tid >> 4;

    float acc[8][8];
#pragma unroll
    for (int i = 0; i < 8; ++i)
#pragma unroll
        for (int jj = 0; jj < 8; ++jj) acc[i][jj] = 0.f;

    float4 pa[2], pb[4];

#pragma unroll
    for (int q = 0; q < 2; ++q) {
        int idx = tid + q*128; int row = idx >> 2, kq = idx & 3; int m = m0 + row;
        pa[q] = make_float4(0.f,0.f,0.f,0.f);
        if (m < M) pa[q] = *(const float4*)(A + (size_t)m*K + kq*4);
    }
#pragma unroll
    for (int q = 0; q < 4; ++q) {
        int idx = tid + q*128; int row = idx >> 2, kq = idx & 3; int n = n0 + row;
        pb[q] = make_float4(0.f,0.f,0.f,0.f);
        if (n < N) pb[q] = *(const float4*)(W + (size_t)n*K + kq*4);
    }
#pragma unroll
    for (int q = 0; q < 2; ++q) {
        int idx = tid + q*128; int row = idx >> 2, kq = idx & 3;
        As[0][kq*4+0][row] = pa[q].x; As[0][kq*4+1][row] = pa[q].y;
        As[0][kq*4+2][row] = pa[q].z; As[0][kq*4+3][row] = pa[q].w;
    }
#pragma unroll
    for (int q = 0; q < 4; ++q) {
        int idx = tid + q*128; int row = idx >> 2, kq = idx & 3;
        Bs[0][kq*4+0][row] = pb[q].x; Bs[0][kq*4+1][row] = pb[q].y;
        Bs[0][kq*4+2][row] = pb[q].z; Bs[0][kq*4+3][row] = pb[q].w;
    }
    __syncthreads();

    const int nk = K / BKK;
    for (int kb = 0; kb < nk; ++kb) {
        const int cur = kb & 1, nxt = cur ^ 1;
        const bool more = (kb + 1 < nk);
        if (more) {
            const int k0 = (kb + 1) * BKK;
#pragma unroll
            for (int q = 0; q < 2; ++q) {
                int idx = tid + q*128; int row = idx >> 2, kq = idx & 3; int m = m0 + row;
                pa[q] = make_float4(0.f,0.f,0.f,0.f);
                if (m < M) pa[q] = *(const float4*)(A + (size_t)m*K + k0 + kq*4);
            }
#pragma unroll
            for (int q = 0; q < 4; ++q) {
                int idx = tid + q*128; int row = idx >> 2, kq = idx & 3; int n = n0 + row;
                pb[q] = make_float4(0.f,0.f,0.f,0.f);
                if (n < N) pb[q] = *(const float4*)(W + (size_t)n*K + k0 + kq*4);
            }
        }
#pragma unroll
        for (int k = 0; k < BKK; ++k) {
            float4 a0 = *(const float4*)&As[cur][k][ty*8];
            float4 a1 = *(const float4*)&As[cur][k][ty*8 + 4];
            float4 b0 = *(const float4*)&Bs[cur][k][tx*8];
            float4 b1 = *(const float4*)&Bs[cur][k][tx*8 + 4];
            float av[8] = {a0.x,a0.y,a0.z,a0.w,a1.x,a1.y,a1.z,a1.w};
            float bv[8] = {b0.x,b0.y,b0.z,b0.w,b1.x,b1.y,b1.z,b1.w};
#pragma unroll
            for (int i = 0; i < 8; ++i)
#pragma unroll
                for (int jj = 0; jj < 8; ++jj)
                    acc[i][jj] += av[i] * bv[jj];
        }
        if (more) {
#pragma unroll
            for (int q = 0; q < 2; ++q) {
                int idx = tid + q*128; int row = idx >> 2, kq = idx & 3;
                As[nxt][kq*4+0][row] = pa[q].x; As[nxt][kq*4+1][row] = pa[q].y;
                As[nxt][kq*4+2][row] = pa[q].z; As[nxt][kq*4+3][row] = pa[q].w;
            }
#pragma unroll
            for (int q = 0; q < 4; ++q) {
                int idx = tid + q*128; int row = idx >> 2, kq = idx & 3;
                Bs[nxt][kq*4+0][row] = pb[q].x; Bs[nxt][kq*4+1][row] = pb[q].y;
                Bs[nxt][kq*4+2][row] = pb[q].z; Bs[nxt][kq*4+3][row] = pb[q].w;
            }
        }
        __syncthreads();
    }

#pragma unroll
    for (int i = 0; i < 8; ++i) {
        int m = m0 + ty*8 + i;
        if (m >= M) continue;
#pragma unroll
        for (int jj = 0; jj < 8; ++jj) {
            int n = n0 + tx*8 + jj;
            if (n < N) C[(size_t)m*N + n] = acc[i][jj] + bias[n];
        }
    }
}

// ---------------- fp16 HMMA GEMM (e1, mid, logits) --------------------
// C[m,n] = bias[n] + sum_k A[m,k]*W[n,k]. fp32 accumulate, m16n8k16.
// 128 threads = 4 warps: 2(M) x 2(N); warp tile 32x64. BM=64 BN=128, BK=32 halfs.
#define TM 64
#define TN 128
#define HK 32          /* halfs per k-chunk */
#define HSTR 20        /* uint32 (half2) stride per row */

__device__ __forceinline__ uint32_t f2h2(float a, float b) {
    __half2 h = __floats2half2_rn(a, b);   // low = a (earlier k), high = b
    return *(uint32_t*)&h;
}

__global__ void __launch_bounds__(128, 2)
mma_f16_tn(const float* __restrict__ A, const float* __restrict__ W,
           const float* __restrict__ bias, float* __restrict__ C,
           int M, int N, int K)
{
    __shared__ uint32_t As[2][TM][HSTR];
    __shared__ uint32_t Bs[2][TN][HSTR];

    const int tid  = threadIdx.x;
    const int lane = tid & 31;
    const int g    = lane >> 2;      // 0..7
    const int tig  = lane & 3;       // 0..3
    const int warp = tid >> 5;       // 0..3
    const int wM   = warp >> 1;      // 0..1
    const int wN   = warp & 1;       // 0..1

    const int m0 = blockIdx.y * TM;
    const int n0 = blockIdx.x * TN;

    const int arow = tid >> 1;
    const int akq  = (tid & 1) * 16;
    const bool aok = (m0 + arow) < M;
    const bool bok = (n0 + tid) < N;

    float c[2][8][4];
#pragma unroll
    for (int mt = 0; mt < 2; ++mt)
#pragma unroll
        for (int j = 0; j < 8; ++j)
#pragma unroll
            for (int i = 0; i < 4; ++i) c[mt][j][i] = 0.f;

    float4 pa[4], pb[8];

#pragma unroll
    for (int q = 0; q < 4; ++q) {
        pa[q] = make_float4(0.f,0.f,0.f,0.f);
        if (aok) pa[q] = *(const float4*)(A + (size_t)(m0 + arow)*K + akq + q*4);
    }
#pragma unroll
    for (int q = 0; q < 8; ++q) {
        pb[q] = make_float4(0.f,0.f,0.f,0.f);
        if (bok) pb[q] = *(const float4*)(W + (size_t)(n0 + tid)*K + q*4);
    }
    {
        uint32_t* ad = &As[0][arow][(tid & 1) * 8];
#pragma unroll
        for (int q = 0; q < 4; ++q) {
            ad[q*2+0] = f2h2(pa[q].x, pa[q].y);
            ad[q*2+1] = f2h2(pa[q].z, pa[q].w);
        }
        uint32_t* bd = &Bs[0][tid][0];
#pragma unroll
        for (int q = 0; q < 8; ++q) {
            bd[q*2+0] = f2h2(pb[q].x, pb[q].y);
            bd[q*2+1] = f2h2(pb[q].z, pb[q].w);
        }
    }
    __syncthreads();

    const int nk = K / HK;
    for (int kb = 0; kb < nk; ++kb) {
        const int cur = kb & 1, nxt = cur ^ 1;
        const bool more = (kb + 1 < nk);
        if (more) {
            const int k0 = (kb + 1) * HK;
#pragma unroll
            for (int q = 0; q < 4; ++q) {
                pa[q] = make_float4(0.f,0.f,0.f,0.f);
                if (aok) pa[q] = *(const float4*)(A + (size_t)(m0 + arow)*K + k0 + akq + q*4);
            }
#pragma unroll
            for (int q = 0; q < 8; ++q) {
                pb[q] = make_float4(0.f,0.f,0.f,0.f);
                if (bok) pb[q] = *(const float4*)(W + (size_t)(n0 + tid)*K + k0 + q*4);
            }
        }

#pragma unroll
        for (int ksub = 0; ksub < 2; ++ksub) {
            const int base = ksub * 8;
            uint32_t a[2][4];
#pragma unroll
            for (int mt = 0; mt < 2; ++mt) {
                const uint32_t* ar = &As[cur][wM*32 + mt*16 + g][base + tig];
                a[mt][0] = ar[0];
                a[mt][1] = ar[8*HSTR];
                a[mt][2] = ar[4];
                a[mt][3] = ar[8*HSTR + 4];
            }
#pragma unroll
            for (int j = 0; j < 8; ++j) {
                const uint32_t* br = &Bs[cur][wN*64 + j*8 + g][base + tig];
                uint32_t b0 = br[0];
                uint32_t b1 = br[4];
#pragma unroll
                for (int mt = 0; mt < 2; ++mt) {
                    asm volatile(
                        "mma.sync.aligned.m16n8k16.row.col.f32.f16.f16.f32 "
                        "{%0,%1,%2,%3}, {%4,%5,%6,%7}, {%8,%9}, {%0,%1,%2,%3};\n"
                        : "+f"(c[mt][j][0]), "+f"(c[mt][j][1]),
                          "+f"(c[mt][j][2]), "+f"(c[mt][j][3])
                        : "r"(a[mt][0]), "r"(a[mt][1]), "r"(a[mt][2]), "r"(a[mt][3]),
                          "r"(b0), "r"(b1));
                }
            }
        }

        if (more) {
            uint32_t* ad = &As[nxt][arow][(tid & 1) * 8];
#pragma unroll
            for (int q = 0; q < 4; ++q) {
                ad[q*2+0] = f2h2(pa[q].x, pa[q].y);
                ad[q*2+1] = f2h2(pa[q].z, pa[q].w);
            }
            uint32_t* bd = &Bs[nxt][tid][0];
#pragma unroll
            for (int q = 0; q < 8; ++q) {
                bd[q*2+0] = f2h2(pb[q].x, pb[q].y);
                bd[q*2+1] = f2h2(pb[q].z, pb[q].w);
            }
        }
        __syncthreads();
    }

    // epilogue: c0,c1 -> row g cols 2*tig..+1; c2,c3 -> row g+8
#pragma unroll
    for (int mt = 0; mt < 2; ++mt) {
        const int row0 = m0 + wM*32 + mt*16 + g;
        const int row1 = row0 + 8;
#pragma unroll
        for (int j = 0; j < 8; ++j) {
            int n = n0 + wN*64 + j*8 + tig*2;
            if (n < N) {
                float bv = bias[n];
                if (row0 < M) C[(size_t)row0*N + n] = c[mt][j][0] + bv;
                if (row1 < M) C[(size_t)row1*N + n] = c[mt][j][2] + bv;
            }
            if (n + 1 < N) {
                float bv = bias[n+1];
                if (row0 < M) C[(size_t)row0*N + n+1] = c[mt][j][1] + bv;
                if (row1 < M) C[(size_t)row1*N + n+1] = c[mt][j][3] + bv;
            }
        }
    }
}

// ---------------- attention scores + softmax -> atten ----------------
__global__ void __launch_bounds__(256)
attn_kernel(const int* __restrict__ sou, const float* __restrict__ v_w,
            float* __restrict__ out)
{
    const int row = blockIdx.x;
    const int b = row / TT;
    const int tid = threadIdx.x;
    const int warp = tid >> 5, lane = tid & 31;
    const float NEG_INF = __int_as_float(0xff800000);

    __shared__ float e2s[HH];
    __shared__ float vs[HH];
    __shared__ float sc[SS];
    __shared__ float red[8];

    e2s[tid]       = g_e2[(size_t)row*HH + tid];
    e2s[tid + 256] = g_e2[(size_t)row*HH + tid + 256];
    vs[tid]        = v_w[tid];
    vs[tid + 256]  = v_w[tid + 256];
    __syncthreads();

    for (int s = warp; s < SS; s += 8) {
        const float* e1r = g_e1 + ((size_t)(b*SS + s)) * HH;
        float acc = 0.f;
#pragma unroll
        for (int k = 0; k < HH/32; ++k) {
            int h = lane + k*32;
            acc += tanhf(e1r[h] + e2s[h]) * vs[h];
        }
#pragma unroll
        for (int o = 16; o; o >>= 1) acc += __shfl_xor_sync(0xffffffffu, acc, o);
        if (lane == 0)
            sc[s] = (sou[b*SS + s] == 0) ? NEG_INF : acc;
    }
    __syncthreads();

    float v0 = sc[tid];
    float m = v0;
#pragma unroll
    for (int o = 16; o; o >>= 1) m = fmaxf(m, __shfl_xor_sync(0xffffffffu, m, o));
    if (lane == 0) red[warp] = m;
    __syncthreads();
    float M = red[0];
#pragma unroll
    for (int w = 1; w < 8; ++w) M = fmaxf(M, red[w]);
    __syncthreads();
    float e = __expf(v0 - M);
    float ssum = e;
#pragma unroll
    for (int o = 16; o; o >>= 1) ssum += __shfl_xor_sync(0xffffffffu, ssum, o);
    if (lane == 0) red[warp] = ssum;
    __syncthreads();
    float Ssum = 0.f;
#pragma unroll
    for (int w = 0; w < 8; ++w) Ssum += red[w];

    float p = e / Ssum;
    g_atten[(size_t)row*SS + tid] = p;
    out[OUT_ATT_OFF + (size_t)row*SS + tid] = p;
}

// ---------------- weighted = atten @ enc ; build all_out --------------
__global__ void __launch_bounds__(128)
weighted_kernel(const float* __restrict__ enc)
{
    const int row = blockIdx.x;
    const int b = row / TT;
    const int tid = threadIdx.x;

    __shared__ float att[SS];
    att[tid]       = g_atten[(size_t)row*SS + tid];
    att[tid + 128] = g_atten[(size_t)row*SS + tid + 128];
    __syncthreads();

    const float4* encb = (const float4*)enc;
    float4 acc = make_float4(0.f,0.f,0.f,0.f);
#pragma unroll 4
    for (int s = 0; s < SS; ++s) {
        float a = att[s];
        float4 ev = encb[((size_t)(b*SS + s)) * (HH/4) + tid];
        acc.x += a*ev.x; acc.y += a*ev.y; acc.z += a*ev.z; acc.w += a*ev.w;
    }
    float4* ao = (float4*)(g_allout + (size_t)row * 2*HH);
    ao[tid] = acc;
    float4 dv = ((const float4*)(g_x + ((size_t)3*ROWS + row)*HH))[tid];
    ao[HH/4 + tid] = dv;
}

// ---------------- copy gate --------------------------------------------
__global__ void __launch_bounds__(128)
gate_kernel(const float* __restrict__ g1w, const float* __restrict__ g1b,
            const float* __restrict__ g2w, const float* __restrict__ g2b,
            const float* __restrict__ g3w, const float* __restrict__ g3b)
{
    const int row = blockIdx.x;
    const int tid = threadIdx.x;
    const int lane = tid & 31, warp = tid >> 5;
    __shared__ float red[4];

    const float* ao = g_allout + (size_t)row * 2*HH;
    const float* te = g_tar_emb + (size_t)row * HH;
    float part = 0.f;
    for (int i = tid; i < HH; i += 128)
        part += ao[i]*g1w[i] + ao[HH + i]*g2w[i] + te[i]*g3w[i];
#pragma unroll
    for (int o = 16; o; o >>= 1) part += __shfl_xor_sync(0xffffffffu, part, o);
    if (lane == 0) red[warp] = part;
    __syncthreads();
    if (tid == 0) {
        float s = red[0] + red[1] + red[2] + red[3] + g1b[0] + g2b[0] + g3b[0];
        g_gate[row] = 1.f / (1.f + expf(-s));
    }
}

// ---------------- logits row softmax stats ------------------------------
__global__ void __launch_bounds__(256)
stats_kernel(const int* __restrict__ ext_len)
{
    const int row = blockIdx.x;
    const int b = row / TT;
    const int tid = threadIdx.x;
    const int lane = tid & 31, warp = tid >> 5;
    const int limit = NVOC + ext_len[b];
    const float* lr = g_logits + (size_t)row * NVEXT;
    const float NEG_INF = __int_as_float(0xff800000);
    __shared__ float red[8];

    float m = NEG_INF;
    for (int c = tid; c < limit; c += 256) m = fmaxf(m, lr[c]);
#pragma unroll
    for (int o = 16; o; o >>= 1) m = fmaxf(m, __shfl_xor_sync(0xffffffffu, m, o));
    if (lane == 0) red[warp] = m;
    __syncthreads();
    float M = red[0];
#pragma unroll
    for (int w = 1; w < 8; ++w) M = fmaxf(M, red[w]);
    __syncthreads();

    float s = 0.f;
    for (int c = tid; c < limit; c += 256) s += __expf(lr[c] - M);
#pragma unroll
    for (int o = 16; o; o >>= 1) s += __shfl_xor_sync(0xffffffffu, s, o);
    if (lane == 0) red[warp] = s;
    __syncthreads();
    if (tid == 0) {
        float S = 0.f;
#pragma unroll
        for (int w = 0; w < 8; ++w) S += red[w];
        g_rowmax[row] = M;
        g_rowsum[row] = S;
    }
}

// ---------------- (1-gate)*softmax(logits) -> out -----------------------
__global__ void __launch_bounds__(256)
gen_kernel(const int* __restrict__ ext_len, float* __restrict__ out)
{
    const int row = blockIdx.y;
    const int c = blockIdx.x * 256 + threadIdx.x;
    if (c >= NVEXT) return;
    const int b = row / TT;
    const int limit = NVOC + ext_len[b];
    const float gate = g_gate[row];
    float val = 0.f;
    if (c < limit)
        val = __expf(g_logits[(size_t)row*NVEXT + c] - g_rowmax[row]) / g_rowsum[row];
    out[(size_t)row*NVEXT + c] = (1.f - gate) * val;
}

// ---------------- copy mechanism: scatter-add gate*atten ---------------
__global__ void __launch_bounds__(256)
scatter_kernel(const int* __restrict__ sou, float* __restrict__ out)
{
    const int row = blockIdx.x;
    const int b = row / TT;
    const int s = threadIdx.x;
    const float add = g_gate[row] * g_atten[(size_t)row*SS + s];
    atomicAdd(&out[(size_t)row*NVEXT + sou[b*SS + s]], add);
}

// ---------------- launcher ---------------------------------------------
extern "C" void kernel_launch(void* const* d_in, const int* in_sizes, int n_in,
                              void* d_out, int out_size)
{
    const int*   sou      = (const int*)  d_in[0];
    const int*   tar      = (const int*)  d_in[1];
    const float* hidden   = (const float*)d_in[2];
    const float* enc      = (const float*)d_in[3];
    const int*   ext_len  = (const int*)  d_in[4];
    const float* emb      = (const float*)d_in[5];
    const float* gru_wih  = (const float*)d_in[6];
    const float* gru_whh  = (const float*)d_in[7];
    const float* gru_bih  = (const float*)d_in[8];
    const float* gru_bhh  = (const float*)d_in[9];
    const float* fc_enc_w = (const float*)d_in[10];
    const float* fc_enc_b = (const float*)d_in[11];
    const float* fc_dec_w = (const float*)d_in[12];
    const float* fc_dec_b = (const float*)d_in[13];
    const float* v_w      = (const float*)d_in[14];
    const float* fc_out1_w= (const float*)d_in[15];
    const float* fc_out1_b= (const float*)d_in[16];
    const float* fc_out2_w= (const float*)d_in[17];
    const float* fc_out2_b= (const float*)d_in[18];
    const float* g1w      = (const float*)d_in[19];
    const float* g1b      = (const float*)d_in[20];
    const float* g2w      = (const float*)d_in[21];
    const float* g2b      = (const float*)d_in[22];
    const float* g3w      = (const float*)d_in[23];
    const float* g3b      = (const float*)d_in[24];
    float* out = (float*)d_out;

    float *p_e1, *p_e2, *p_x, *p_allout, *p_mid, *p_logits;
    cudaGetSymbolAddress((void**)&p_e1,     g_e1);
    cudaGetSymbolAddress((void**)&p_e2,     g_e2);
    cudaGetSymbolAddress((void**)&p_x,      g_x);
    cudaGetSymbolAddress((void**)&p_allout, g_allout);
    cudaGetSymbolAddress((void**)&p_mid,    g_mid);
    cudaGetSymbolAddress((void**)&p_logits, g_logits);
    const float* p_dec = p_x + (size_t)3*ROWS*HH;

    setup_kernel<<<1, 256>>>(tar, hidden);
    embed_kernel<<<ROWS, 128>>>(tar, emb);
    gru_kernel<<<GRU_BLOCKS, 128>>>(gru_wih, gru_whh, gru_bih, gru_bhh);

    // e1 = enc @ fc_enc_w^T + b   [2048, 512]  (fp16 HMMA)
    mma_f16_tn<<<dim3((HH+TN-1)/TN, (BB*SS+TM-1)/TM), 128>>>(enc, fc_enc_w, fc_enc_b, p_e1, BB*SS, HH, HH);
    // e2 = dec_out @ fc_dec_w^T + b  [400, 512]  (fp32 hedge)
    sgemm_tn<<<dim3((HH+BN-1)/BN, (ROWS+BM-1)/BM), 128>>>(p_dec, fc_dec_w, fc_dec_b, p_e2, ROWS, HH, HH);

    attn_kernel<<<ROWS, 256>>>(sou, v_w, out);
    weighted_kernel<<<ROWS, 128>>>(enc);
    gate_kernel<<<ROWS, 128>>>(g1w, g1b, g2w, g2b, g3w, g3b);

    // mid = all_out @ fc_out2_w^T + b  [400, 512], K=1024  (fp16 HMMA)
    mma_f16_tn<<<dim3((HH+TN-1)/TN, (ROWS+TM-1)/TM), 128>>>(p_allout, fc_out2_w, fc_out2_b, p_mid, ROWS, HH, 2*HH);
    // logits = mid @ fc_out1_w^T + b  [400, 50256]  (fp16 HMMA)
    mma_f16_tn<<<dim3((NVEXT+TN-1)/TN, (ROWS+TM-1)/TM), 128>>>(p_mid, fc_out1_w, fc_out1_b, p_logits, ROWS, NVEXT, HH);

    stats_kernel<<<ROWS, 256>>>(ext_len);
    gen_kernel<<<dim3((NVEXT+255)/256, ROWS), 256>>>(ext_len, out);
    scatter_kernel<<<ROWS, 256>>>(sou, out);
}